// round 17
// baseline (speedup 1.0000x reference)
#include <cuda_runtime.h>
#include <cuda_fp16.h>
#include <cstdint>
#include <cstring>

// Dual LSTM B=512 T=128 I=128 H=512 — persistent kernel, 128 CTAs x 512 thr.
// W resident in smem (162 KB); A via 6-stage cp.async ring, 2 tiles per sync;
// split arrive/wait grid barrier overlapped with x-only tiles; fp16 mma+ldmatrix.

#define B_   512
#define T_   128
#define I_   128
#define H_   512
#define K_   640
#define G4_  2048

#define NBLK     128
#define NTHREADS 512

#define W_STRIDE 324                        // words per pcol row (4-word bank step)
#define W_BYTES  (128 * W_STRIDE * 4)       // 165888
#define A_STAGE_BYTES (128 * 80)            // 10240 (128 rows x 80B)
#define A_OFF    W_BYTES
#define NSTAGE   6
#define SMEM_BYTES (W_BYTES + NSTAGE * A_STAGE_BYTES)   // 227328

__device__ __half   g_x16[2][(size_t)B_ * T_ * I_];
__device__ __half   g_Wn[2][(size_t)G4_ * K_];   // [pcol][k], gate-interleaved pcol
__device__ __half   g_h16[2][2][(size_t)B_ * H_];
__device__ unsigned g_arrive[9];
__device__ unsigned g_release[9];

__device__ __forceinline__ unsigned f2tf32(float x) {
    unsigned u; asm("cvt.rna.tf32.f32 %0, %1;" : "=r"(u) : "f"(x)); return u;
}
__device__ __forceinline__ float tanh_a(float x) {
    float r; asm("tanh.approx.f32 %0, %1;" : "=f"(r) : "f"(x)); return r;
}
__device__ __forceinline__ float sigm_a(float x) {
    return fmaf(tanh_a(0.5f * x), 0.5f, 0.5f);
}

__device__ __forceinline__ void ldsm4(unsigned* r, uint32_t a) {
    asm volatile("ldmatrix.sync.aligned.m8n8.x4.shared.b16 {%0,%1,%2,%3}, [%4];"
                 : "=r"(r[0]), "=r"(r[1]), "=r"(r[2]), "=r"(r[3]) : "r"(a));
}
__device__ __forceinline__ uint32_t smem_u32(const void* p) {
    uint32_t a;
    asm("{ .reg .u64 t; cvta.to.shared.u64 t, %1; cvt.u32.u64 %0, t; }" : "=r"(a) : "l"(p));
    return a;
}
__device__ __forceinline__ void cpa16(uint32_t saddr, const void* g) {
    asm volatile("cp.async.cg.shared.global [%0], [%1], 16;"
                 :: "r"(saddr), "l"(g) : "memory");
}
#define CP_COMMIT()  asm volatile("cp.async.commit_group;" ::: "memory")
#define CP_WAITG(n)  asm volatile("cp.async.wait_group %0;" :: "n"(n) : "memory")

__device__ __forceinline__ void mma16(float* d, const unsigned* a, const unsigned* b) {
    asm volatile(
        "mma.sync.aligned.m16n8k16.row.col.f32.f16.f16.f32 "
        "{%0,%1,%2,%3}, {%4,%5,%6,%7}, {%8,%9}, {%0,%1,%2,%3};\n"
        : "+f"(d[0]), "+f"(d[1]), "+f"(d[2]), "+f"(d[3])
        : "r"(a[0]), "r"(a[1]), "r"(a[2]), "r"(a[3]), "r"(b[0]), "r"(b[1]));
}
__device__ __forceinline__ void mma8t(float* d, const unsigned* a, const unsigned* b) {
    asm volatile(
        "mma.sync.aligned.m16n8k8.row.col.f32.tf32.tf32.f32 "
        "{%0,%1,%2,%3}, {%4,%5,%6,%7}, {%8,%9}, {%0,%1,%2,%3};\n"
        : "+f"(d[0]), "+f"(d[1]), "+f"(d[2]), "+f"(d[3])
        : "r"(a[0]), "r"(a[1]), "r"(a[2]), "r"(a[3]), "r"(b[0]), "r"(b[1]));
}

// split barrier: arrive returns the generation to wait for (valid in thread 0)
__device__ __forceinline__ unsigned garrive(int idx, unsigned n) {
    __syncthreads();
    unsigned gen = 0;
    if (threadIdx.x == 0) {
        unsigned t;
        asm volatile("atom.add.acq_rel.gpu.global.u32 %0, [%1], 1;"
                     : "=r"(t) : "l"(&g_arrive[idx]) : "memory");
        t += 1u;
        gen = (t + n - 1u) / n;
        if (t == gen * n) {
            unsigned d;
            asm volatile("atom.add.release.gpu.global.u32 %0, [%1], 1;"
                         : "=r"(d) : "l"(&g_release[idx]) : "memory");
        }
    }
    return gen;
}
__device__ __forceinline__ void gwait(int idx, unsigned gen) {
    if (threadIdx.x == 0) {
        unsigned r;
        for (;;) {
            asm volatile("ld.acquire.gpu.u32 %0, [%1];" : "=r"(r) : "l"(&g_release[idx]) : "memory");
            if (r >= gen) break;
        }
    }
    __syncthreads();
}
__device__ __forceinline__ void gsync(int idx, unsigned n) {
    unsigned g = garrive(idx, n);
    gwait(idx, g);
}

__device__ __forceinline__ void st_h2(__half* p, float v0, float v1) {
    __half2 h = __floats2half2_rn(v0, v1);
    unsigned u; memcpy(&u, &h, 4);
    asm volatile("st.global.cg.u32 [%0], %1;" :: "l"(p), "r"(u) : "memory");
}

// pcol -> (gate, global hidden col) mapping (must match main kernel fragments)
__device__ __forceinline__ void pcol_map(int pcol, int& gate, int& n) {
    int slice = pcol >> 7;
    int lp    = pcol & 127;
    int wn    = lp >> 5;
    int r     = lp & 31;
    int nf    = r >> 3;
    int p     = r & 7;
    gate = (nf & 1) * 2 + (p & 1);
    n    = slice * 32 + wn * 8 + (nf >> 1) + (p >> 1) * 2;
}

// ---------------- prepass kernels ----------------
extern "C" __global__ void prep_x_kernel(const float* __restrict__ sx,
                                         const float* __restrict__ lx) {
    const int PER = B_ * T_ * I_ / 4;
    int i = blockIdx.x * blockDim.x + threadIdx.x;
    if (i >= 2 * PER) return;
    int cell = (i >= PER);
    int j = i - cell * PER;
    const float* src = cell ? lx : sx;
    float4 v = __ldg((const float4*)src + j);
    __half2* dst = (__half2*)(g_x16[cell]) + j * 2;
    dst[0] = __floats2half2_rn(v.x, v.y);
    dst[1] = __floats2half2_rn(v.z, v.w);
}

extern "C" __global__ void prep_w_kernel(const float* __restrict__ sW,
                                         const float* __restrict__ lW) {
    const int PER = G4_ * (K_ / 8);
    int i = blockIdx.x * blockDim.x + threadIdx.x;
    if (i >= 2 * PER) return;
    int cell = (i >= PER);
    int r = i - cell * PER;
    int pcol = r / (K_ / 8);
    int kg   = r % (K_ / 8);
    int gate, n;
    pcol_map(pcol, gate, n);
    const float* W = cell ? lW : sW;
    int wc = gate * H_ + n;
    __half tmp[8];
    #pragma unroll
    for (int k = 0; k < 8; ++k)
        tmp[k] = __float2half_rn(__ldg(W + (size_t)(kg * 8 + k) * G4_ + wc));
    uint4 o; memcpy(&o, tmp, 16);
    *(uint4*)(&g_Wn[cell][(size_t)pcol * K_ + kg * 8]) = o;
}

// ---------------- compute one k-tile ----------------
__device__ __forceinline__ void compute_tile(float acc[2][4][4], uint32_t sA,
                                             uint32_t bk) {
    #pragma unroll
    for (int kc = 0; kc < 2; ++kc) {
        unsigned af[2][4], bf[4][4];
        #pragma unroll
        for (int mf = 0; mf < 2; ++mf)
            ldsm4(af[mf], sA + mf * (16 * 80) + kc * 32);
        #pragma unroll
        for (int nfp = 0; nfp < 2; ++nfp)
            ldsm4(bf[nfp * 2], bk + nfp * (16 * W_STRIDE * 4) + kc * 32);
        #pragma unroll
        for (int mf = 0; mf < 2; ++mf) {
            #pragma unroll
            for (int nfp = 0; nfp < 2; ++nfp) {
                mma16(acc[mf][nfp * 2],     af[mf], &bf[nfp * 2][0]);
                mma16(acc[mf][nfp * 2 + 1], af[mf], &bf[nfp * 2][2]);
            }
        }
    }
}

// ---------------- main persistent kernel ----------------
extern "C" __global__ void __launch_bounds__(NTHREADS, 1)
dual_lstm_kernel(const float* __restrict__ s_b, const float* __restrict__ l_b,
                 const float* __restrict__ oW,  const float* __restrict__ ob,
                 float* __restrict__ out)
{
    extern __shared__ unsigned char smem_raw[];
    unsigned* Wsm = (unsigned*)smem_raw;
    const uint32_t smem_b32 = smem_u32(smem_raw);

    const int tid  = threadIdx.x;
    const int bid  = blockIdx.x;
    const int cell = bid >> 6;
    const int rr   = bid & 63;
    const int b0   = (rr >> 4) * 128;
    const int n0   = (rr & 15) * 32;
    const int pbase = (rr & 15) * 128;
    const int grp  = (cell << 2) | (rr >> 4);

    const __half* x16 = g_x16[cell];
    const __half* Wn  = g_Wn[cell];
    const float*  bb  = cell ? l_b : s_b;

    const int warp = tid >> 5, lane = tid & 31;
    const int wm = warp >> 2, wn = warp & 3;
    const int q  = lane >> 2, cl = lane & 3;

    // ---- load W slice into smem once ----
    for (int i = tid; i < 128 * 80; i += NTHREADS) {
        int pcol = i / 80, kg = i % 80;
        uint4 v = __ldg((const uint4*)(Wn + (size_t)(pbase + pcol) * K_ + kg * 8));
        *(uint4*)(Wsm + pcol * W_STRIDE + kg * 4) = v;
    }

    const int ncol0 = n0 + wn * 8 + 2 * cl;
    float bias_g[2][4];
    #pragma unroll
    for (int j = 0; j < 2; ++j)
        #pragma unroll
        for (int g = 0; g < 4; ++g)
            bias_g[j][g] = bb[g * H_ + ncol0 + j];

    #pragma unroll
    for (int mf = 0; mf < 2; ++mf)
        #pragma unroll
        for (int r = 0; r < 2; ++r) {
            int row = b0 + wm * 32 + mf * 16 + q + r * 8;
            st_h2(&g_h16[cell][0][(size_t)row * H_ + ncol0], 0.0f, 0.0f);
        }

    float c_st[8];
    #pragma unroll
    for (int i = 0; i < 8; ++i) c_st[i] = 0.0f;

    // A fill / fragment constants
    const int fa_row = tid >> 2;
    const int fa_k8  = (tid & 3) << 3;
    const uint32_t fa_woff = (uint32_t)(fa_row * 80 + (tid & 3) * 16);
    const uint32_t a_frag_off = (uint32_t)((lane & 15) * 80 + (lane >> 4) * 16);
    const uint32_t a_warp_off = (uint32_t)((wm * 32) * 80) + a_frag_off;
    const uint32_t b_pcol = (uint32_t)((lane >> 4) * 8 + (lane & 7));
    const uint32_t b_base = smem_b32 + (wn * 32 + b_pcol) * (W_STRIDE * 4) +
                            ((lane >> 3) & 1) * 16;
    const uint32_t a_stage_base = smem_b32 + A_OFF;

    unsigned bar_gen = garrive(grp, 16);   // publishes h zeros + own W smem done

    // ================== time loop ==================
    for (int t = 0; t < T_; ++t) {
        const __half* hread  = g_h16[cell][t & 1];
        __half*       hwrite = g_h16[cell][(t + 1) & 1];
        const __half* x_t  = x16 + ((size_t)(b0 + fa_row) * T_ + t) * I_ + fa_k8;
        const __half* h_rw = hread + (size_t)(b0 + fa_row) * H_ + fa_k8;

        float acc[2][4][4];
        #pragma unroll
        for (int a = 0; a < 2; ++a)
            #pragma unroll
            for (int nb = 0; nb < 4; ++nb)
                #pragma unroll
                for (int r = 0; r < 2; ++r) {
                    acc[a][nb][2 * r]     = bias_g[nb >> 1][(nb & 1) * 2];
                    acc[a][nb][2 * r + 1] = bias_g[nb >> 1][(nb & 1) * 2 + 1];
                }

        // issue x pairs G0 (tiles 0,1) and G1 (tiles 2,3)
        cpa16(a_stage_base + 0 * A_STAGE_BYTES + fa_woff, x_t + 0 * 32);
        cpa16(a_stage_base + 1 * A_STAGE_BYTES + fa_woff, x_t + 1 * 32);
        CP_COMMIT();
        cpa16(a_stage_base + 2 * A_STAGE_BYTES + fa_woff, x_t + 2 * 32);
        cpa16(a_stage_base + 3 * A_STAGE_BYTES + fa_woff, x_t + 3 * 32);
        CP_COMMIT();

        // pair 0 (x)
        CP_WAITG(1); __syncthreads();
        compute_tile(acc, a_stage_base + 0 * A_STAGE_BYTES + a_warp_off, b_base + 0 * 64);
        compute_tile(acc, a_stage_base + 1 * A_STAGE_BYTES + a_warp_off, b_base + 1 * 64);

        // pair 1 (x); then barrier-wait and launch first h pairs
        CP_WAITG(0); __syncthreads();
        gwait(grp, bar_gen);                 // h(t) now visible; overlapped with pair 0
        cpa16(a_stage_base + 4 * A_STAGE_BYTES + fa_woff, h_rw + (4 * 32 - I_));
        cpa16(a_stage_base + 5 * A_STAGE_BYTES + fa_woff, h_rw + (5 * 32 - I_));
        CP_COMMIT();
        cpa16(a_stage_base + 0 * A_STAGE_BYTES + fa_woff, h_rw + (6 * 32 - I_));
        cpa16(a_stage_base + 1 * A_STAGE_BYTES + fa_woff, h_rw + (7 * 32 - I_));
        CP_COMMIT();
        compute_tile(acc, a_stage_base + 2 * A_STAGE_BYTES + a_warp_off, b_base + 2 * 64);
        compute_tile(acc, a_stage_base + 3 * A_STAGE_BYTES + a_warp_off, b_base + 3 * 64);

        // pairs 2..8: wait G_pp, issue G_{pp+2}, compute
        #pragma unroll 1
        for (int pp = 2; pp <= 8; ++pp) {
            CP_WAITG(1); __syncthreads();
            if (pp <= 7) {
                const int kt = 2 * pp + 4;
                const int s0 = kt % NSTAGE, s1 = (kt + 1) % NSTAGE;
                cpa16(a_stage_base + s0 * A_STAGE_BYTES + fa_woff, h_rw + (kt * 32 - I_));
                cpa16(a_stage_base + s1 * A_STAGE_BYTES + fa_woff, h_rw + (kt * 32 - I_ + 32));
                CP_COMMIT();
            }
            const int k0 = 2 * pp;
            compute_tile(acc, a_stage_base + (k0 % NSTAGE) * A_STAGE_BYTES + a_warp_off,
                         b_base + k0 * 64);
            compute_tile(acc, a_stage_base + ((k0 + 1) % NSTAGE) * A_STAGE_BYTES + a_warp_off,
                         b_base + (k0 + 1) * 64);
        }
        // pair 9
        CP_WAITG(0); __syncthreads();
        compute_tile(acc, a_stage_base + (18 % NSTAGE) * A_STAGE_BYTES + a_warp_off,
                     b_base + 18 * 64);
        compute_tile(acc, a_stage_base + (19 % NSTAGE) * A_STAGE_BYTES + a_warp_off,
                     b_base + 19 * 64);

        // ---- gate math in registers ----
        #pragma unroll
        for (int mf = 0; mf < 2; ++mf) {
            #pragma unroll
            for (int r = 0; r < 2; ++r) {
                float h01[2];
                #pragma unroll
                for (int j = 0; j < 2; ++j) {
                    float f  = acc[mf][j * 2][2 * r];
                    float ii = acc[mf][j * 2][2 * r + 1];
                    float o  = acc[mf][j * 2 + 1][2 * r];
                    float cd = acc[mf][j * 2 + 1][2 * r + 1];
                    int ci = mf * 4 + r * 2 + j;
                    float c = sigm_a(f) * c_st[ci] + sigm_a(ii) * tanh_a(cd);
                    c_st[ci] = c;
                    h01[j] = sigm_a(o) * tanh_a(c);
                }
                int row = b0 + wm * 32 + mf * 16 + q + r * 8;
                st_h2(&hwrite[(size_t)row * H_ + ncol0], h01[0], h01[1]);
            }
        }
        bar_gen = garrive(grp, 16);   // publish h(t+1); wait happens next step
    }

    gsync(8, 128);   // both cells' final h visible everywhere

    // ================== epilogue: out = tanh([sh,lh] @ oW + ob) ==================
    const __half* hs = g_h16[0][0];
    const __half* hl = g_h16[1][0];
    const int b0e = (bid >> 4) * 64;
    const int n0e = (bid & 15) * 32;
    unsigned* As2 = (unsigned*)smem_raw;    // [64][36] tf32
    unsigned* Bs2 = As2 + 64 * 36;          // [32][36] tf32

    const int wm2 = warp & 3;
    const int wn2 = warp >> 2;
    const int rb2 = wm2 * 16;
    const int cb2 = wn2 * 8;
    float acc2[4];
    #pragma unroll
    for (int r = 0; r < 4; ++r) acc2[r] = 0.0f;

    for (int kt = 0; kt < 32; ++kt) {
        const int k0 = kt * 32;
        __syncthreads();
        {
            int m  = tid >> 3;
            int kk = (tid & 7) << 2;
            int k  = k0 + kk;
            const __half* hp = (k < H_) ? (hs + (size_t)(b0e + m) * H_ + k)
                                        : (hl + (size_t)(b0e + m) * H_ + (k - H_));
            uint2 u = __ldcg((const uint2*)hp);
            __half2 p0, p1;
            memcpy(&p0, &u.x, 4);
            memcpy(&p1, &u.y, 4);
            unsigned* d = As2 + m * 36 + kk;
            d[0] = __float_as_uint(__low2float(p0));
            d[1] = __float_as_uint(__high2float(p0));
            d[2] = __float_as_uint(__low2float(p1));
            d[3] = __float_as_uint(__high2float(p1));
        }
        if (tid < 256) {
            int kk = tid >> 3;
            int c  = (tid & 7) << 2;
            float4 v = __ldg((const float4*)(oW + (size_t)(k0 + kk) * H_ + n0e + c));
            unsigned* d = Bs2 + kk * 36 + c;
            d[0] = f2tf32(v.x); d[1] = f2tf32(v.y);
            d[2] = f2tf32(v.z); d[3] = f2tf32(v.w);
        }
        __syncthreads();
        #pragma unroll
        for (int kc = 0; kc < 32; kc += 8) {
            unsigned af[4];
            const unsigned* p = As2 + (rb2 + q) * 36 + kc + cl;
            af[0] = p[0]; af[1] = p[8 * 36]; af[2] = p[4]; af[3] = p[8 * 36 + 4];
            const unsigned* qq = Bs2 + (kc + cl) * 36 + cb2 + q;
            unsigned bf2[2] = { qq[0], qq[4 * 36] };
            mma8t(acc2, af, bf2);
        }
    }

    {
        int row = b0e + rb2 + q;
        int c0  = n0e + cb2 + (cl << 1);
        out[(size_t)row * H_ + c0]           = tanhf(acc2[0] + ob[c0]);
        out[(size_t)row * H_ + c0 + 1]       = tanhf(acc2[1] + ob[c0 + 1]);
        out[(size_t)(row + 8) * H_ + c0]     = tanhf(acc2[2] + ob[c0]);
        out[(size_t)(row + 8) * H_ + c0 + 1] = tanhf(acc2[3] + ob[c0 + 1]);
    }
}

extern "C" void kernel_launch(void* const* d_in, const int* in_sizes, int n_in,
                              void* d_out, int out_size) {
    (void)in_sizes; (void)n_in; (void)out_size;
    const float* s_x = (const float*)d_in[0];
    const float* l_x = (const float*)d_in[1];
    // d_in[2]=dow, d_in[3]=hour : unused by the reference
    const float* s_W = (const float*)d_in[4];
    const float* s_b = (const float*)d_in[5];
    const float* l_W = (const float*)d_in[6];
    const float* l_b = (const float*)d_in[7];
    const float* oW  = (const float*)d_in[8];
    const float* ob  = (const float*)d_in[9];
    float* out = (float*)d_out;

    prep_x_kernel<<<(2 * B_ * T_ * I_ / 4 + 511) / 512, 512>>>(s_x, l_x);
    prep_w_kernel<<<(2 * G4_ * (K_ / 8) + 511) / 512, 512>>>(s_W, l_W);

    cudaFuncSetAttribute(dual_lstm_kernel,
                         cudaFuncAttributeMaxDynamicSharedMemorySize, SMEM_BYTES);
    dual_lstm_kernel<<<NBLK, NTHREADS, SMEM_BYTES>>>(s_b, l_b, oW, ob, out);
}